// round 17
// baseline (speedup 1.0000x reference)
#include <cuda_runtime.h>
#include <cuda_fp16.h>
#include <stdint.h>

#define N_NODES 20000
#define D_IN    128
#define D_H     256
#define D_H4    64                // uint2 (4-half) columns
#define LN_EPS  1e-5f
#define MAX_E   330000
#define NB_SCAN ((N_NODES + 255) / 256)   // 79
#define DEG_SCALE 1048576.0f              // 2^20 fixed-point for edge weights
#define H_SPLIT 10112                     // 79 * 128, pipeline split row

// ---------------- scratch (no dynamic allocation allowed) ----------------
// invariant: g_degcnt == 0 at kernel_launch entry (zeroed statics; scan1
// restores after reading)
__device__ unsigned long long g_degcnt[N_NODES];  // cnt<<40 | deg_fp20
__device__ float  g_dinv[N_NODES];
__device__ int    g_off [N_NODES + 1];
__device__ int    g_cur [N_NODES];        // fill cursor (re-init by scan2)
__device__ int    g_blksum[NB_SCAN];
__device__ int2   g_csr [MAX_E];          // {src, nrm-as-int}
__device__ __half g_h1h [N_NODES * D_H];  // x@W1 (fp16) — read-only after GEMM1
__device__ __half g_h2h [N_NODES * D_H];  // h@W2 (fp16) — separate, no aliasing
__device__ float  g_hres[N_NODES * D_H];  // x@Wres + bres (fp32)
__device__ float  g_h   [N_NODES * D_H];  // after LN1 (fp32)

// ---------------- helpers ----------------
__device__ __forceinline__ uint32_t pack_h2(float a, float b) {
    __half2 h = __floats2half2_rn(a, b);
    return *reinterpret_cast<uint32_t*>(&h);
}

__device__ __forceinline__ void mma_f16(float* c, const uint32_t* a, const uint32_t* b) {
    asm volatile(
        "mma.sync.aligned.m16n8k16.row.col.f32.f16.f16.f32 "
        "{%0,%1,%2,%3}, {%4,%5,%6,%7}, {%8,%9}, {%0,%1,%2,%3};"
        : "+f"(c[0]), "+f"(c[1]), "+f"(c[2]), "+f"(c[3])
        : "r"(a[0]), "r"(a[1]), "r"(a[2]), "r"(a[3]), "r"(b[0]), "r"(b[1]));
}

__device__ __forceinline__ void fma4_h(float4& a, float n, uint2 v) {
    float2 f0 = __half22float2(*reinterpret_cast<__half2*>(&v.x));
    float2 f1 = __half22float2(*reinterpret_cast<__half2*>(&v.y));
    a.x += n * f0.x; a.y += n * f0.y;
    a.z += n * f1.x; a.w += n * f1.y;
}

// ---------------- degree + count via ONE packed 64-bit atomic ---------------
__global__ void degcnt_kernel(const int* __restrict__ dst,
                              const float* __restrict__ w, int E) {
    for (int e = blockIdx.x * blockDim.x + threadIdx.x; e < E;
         e += gridDim.x * blockDim.x) {
        int d = dst[e];
        unsigned long long packed =
            (1ULL << 40) | (unsigned long long)__float2uint_rn(w[e] * DEG_SCALE);
        atomicAdd(&g_degcnt[d], packed);
    }
}

// ---------------- scan pass 1: per-block exclusive scan + dinv --------------
__global__ void scan1_kernel() {
    const int t = threadIdx.x, b = blockIdx.x;
    const int i = b * 256 + t;
    const int lane = t & 31, wid = t >> 5;

    int v = 0;
    if (i < N_NODES) {
        unsigned long long pc = g_degcnt[i];
        g_degcnt[i] = 0ULL;                               // restore invariant
        v = (int)(pc >> 40);
        float d = (float)(pc & 0xFFFFFFFFFFULL) * (1.0f / DEG_SCALE);
        g_dinv[i] = rsqrtf(d + 1.0f);                     // + self-loop
    }

    int s = v;
#pragma unroll
    for (int o = 1; o < 32; o <<= 1) {
        int u = __shfl_up_sync(0xFFFFFFFFu, s, o);
        if (lane >= o) s += u;
    }
    __shared__ int wsum[8];
    if (lane == 31) wsum[wid] = s;
    __syncthreads();
    int base = 0;
#pragma unroll
    for (int w = 0; w < 8; w++) base += (w < wid) ? wsum[w] : 0;
    if (i < N_NODES) g_off[i] = base + s - v;
    if (t == 255) g_blksum[b] = base + s;
}

// ---------------- scan pass 2: add block bases, init fill cursor ------------
__global__ void scan2_kernel(int E) {
    const int t = threadIdx.x, b = blockIdx.x;
    __shared__ int sbase;
    if (t < 32) {
        int acc = 0;
        for (int j = t; j < b; j += 32) acc += g_blksum[j];
#pragma unroll
        for (int o = 16; o; o >>= 1) acc += __shfl_xor_sync(0xFFFFFFFFu, acc, o);
        if (t == 0) sbase = acc;
    }
    __syncthreads();
    const int i = b * 256 + t;
    if (i < N_NODES) {
        int off = g_off[i] + sbase;
        g_off[i] = off;
        g_cur[i] = off;
    }
    if (b == 0 && t == 0) g_off[N_NODES] = E;
}

// ---------------- CSR fill: ONE 8-byte store per edge ----------------
__global__ void fill_kernel(const int* __restrict__ src,
                            const int* __restrict__ dst,
                            const float* __restrict__ w, int E) {
    for (int e = blockIdx.x * blockDim.x + threadIdx.x; e < E;
         e += gridDim.x * blockDim.x) {
        int s = src[e];
        int d = dst[e];
        int pos = atomicAdd(&g_cur[d], 1);
        float nrm = g_dinv[s] * w[e] * g_dinv[d];
        g_csr[pos] = make_int2(s, __float_as_int(nrm));
    }
}

// ---------------- FP16 tensor-core GEMM (row-range [m0, M)) ----------------
// C[M,256] = A[M,K] @ B[K,256] (+bias). BM=128 BN=128 BK=16, 256 thr (8 warps).
template<int K>
__global__ __launch_bounds__(256)
void f16_gemm_kernel(const float* __restrict__ A, int m0, int M, int nb,
                     const float* __restrict__ Bm1, const float* __restrict__ bias1,
                     __half* __restrict__ C1h, float* __restrict__ C1f,
                     const float* __restrict__ Bm2, const float* __restrict__ bias2,
                     __half* __restrict__ C2h, float* __restrict__ C2f) {
    __shared__ uint32_t As2[128][12];
    __shared__ uint32_t Bs2[8][136];

    const int tid  = threadIdx.x;
    const int lane = tid & 31;
    const int wid  = tid >> 5;
    const int wm   = (wid & 1) * 64;
    const int wn   = (wid >> 1) * 32;
    const int g    = lane >> 2;
    const int tg   = lane & 3;

    const int bm  = m0 + blockIdx.x * 128;
    const int mat = blockIdx.y / nb;
    const int bn  = (blockIdx.y % nb) * 128;

    const float* Bw   = mat ? Bm2   : Bm1;
    const float* bias = mat ? bias2 : bias1;
    __half*      Ch   = mat ? C2h   : C1h;
    float*       Cf   = mat ? C2f   : C1f;

    const int a_row = tid >> 1;
    const int a_k   = (tid & 1) * 8;
    const int a_k2  = (tid & 1) * 4;
    const int b_r   = tid >> 5;
    const int b_c   = (tid & 31) * 4;
    const bool a_ok = (bm + a_row) < M;
    const long a_base = (long)(bm + a_row) * K;

    float acc[4][4][4];
#pragma unroll
    for (int mt = 0; mt < 4; mt++)
#pragma unroll
        for (int nt = 0; nt < 4; nt++)
#pragma unroll
            for (int i = 0; i < 4; i++) acc[mt][nt][i] = 0.0f;

    float4 av0 = make_float4(0.f,0.f,0.f,0.f), av1 = av0;
    if (a_ok) {
        av0 = *reinterpret_cast<const float4*>(A + a_base + a_k);
        av1 = *reinterpret_cast<const float4*>(A + a_base + a_k + 4);
    }
    float4 bv0 = *reinterpret_cast<const float4*>(Bw + (long)(2 * b_r)     * D_H + bn + b_c);
    float4 bv1 = *reinterpret_cast<const float4*>(Bw + (long)(2 * b_r + 1) * D_H + bn + b_c);

    const int T = K / 16;
    for (int t = 0; t < T; t++) {
        __syncthreads();
        {
            uint4 pa = make_uint4(pack_h2(av0.x, av0.y), pack_h2(av0.z, av0.w),
                                  pack_h2(av1.x, av1.y), pack_h2(av1.z, av1.w));
            *reinterpret_cast<uint4*>(&As2[a_row][a_k2]) = pa;
            uint4 pb = make_uint4(pack_h2(bv0.x, bv1.x), pack_h2(bv0.y, bv1.y),
                                  pack_h2(bv0.z, bv1.z), pack_h2(bv0.w, bv1.w));
            *reinterpret_cast<uint4*>(&Bs2[b_r][b_c]) = pb;
        }
        __syncthreads();

        if (t + 1 < T) {
            int kt = (t + 1) * 16;
            av0 = make_float4(0.f,0.f,0.f,0.f); av1 = av0;
            if (a_ok) {
                av0 = *reinterpret_cast<const float4*>(A + a_base + kt + a_k);
                av1 = *reinterpret_cast<const float4*>(A + a_base + kt + a_k + 4);
            }
            bv0 = *reinterpret_cast<const float4*>(Bw + (long)(kt + 2 * b_r)     * D_H + bn + b_c);
            bv1 = *reinterpret_cast<const float4*>(Bw + (long)(kt + 2 * b_r + 1) * D_H + bn + b_c);
        }

        uint32_t af[4][4], bf[4][2];
#pragma unroll
        for (int mt = 0; mt < 4; mt++) {
            int r0 = wm + mt * 16 + g;
            af[mt][0] = As2[r0    ][tg    ];
            af[mt][1] = As2[r0 + 8][tg    ];
            af[mt][2] = As2[r0    ][tg + 4];
            af[mt][3] = As2[r0 + 8][tg + 4];
        }
#pragma unroll
        for (int nt = 0; nt < 4; nt++) {
            int c0 = wn + nt * 8 + g;
            bf[nt][0] = Bs2[tg    ][c0];
            bf[nt][1] = Bs2[tg + 4][c0];
        }
#pragma unroll
        for (int mt = 0; mt < 4; mt++)
#pragma unroll
            for (int nt = 0; nt < 4; nt++)
                mma_f16(acc[mt][nt], af[mt], bf[nt]);
    }

#pragma unroll
    for (int mt = 0; mt < 4; mt++) {
        int row = bm + wm + mt * 16 + g;
#pragma unroll
        for (int nt = 0; nt < 4; nt++) {
            int col = bn + wn + nt * 8 + tg * 2;
            float b0 = bias ? bias[col]     : 0.0f;
            float b1 = bias ? bias[col + 1] : 0.0f;
            float v00 = acc[mt][nt][0] + b0, v01 = acc[mt][nt][1] + b1;
            float v10 = acc[mt][nt][2] + b0, v11 = acc[mt][nt][3] + b1;
            if (Ch) {
                if (row < M)
                    *reinterpret_cast<__half2*>(Ch + (long)row * D_H + col) =
                        __floats2half2_rn(v00, v01);
                if (row + 8 < M)
                    *reinterpret_cast<__half2*>(Ch + (long)(row + 8) * D_H + col) =
                        __floats2half2_rn(v10, v11);
            } else {
                if (row < M)
                    *reinterpret_cast<float2*>(Cf + (long)row * D_H + col) =
                        make_float2(v00, v01);
                if (row + 8 < M)
                    *reinterpret_cast<float2*>(Cf + (long)(row + 8) * D_H + col) =
                        make_float2(v10, v11);
            }
        }
    }
}

// ---------------- fused CSR gather: uint2 loads, 4-way edge parity ----------
// 256 threads = 64 uint2-columns x 4 parity groups; 1 dependent L2 round/row.
// processes rows [row0, row0+gridDim.x)
template<bool RELU>
__global__ __launch_bounds__(256)
void gather_ln_kernel(int row0,
                      const __half* __restrict__ feat,
                      const float* __restrict__ resid,
                      const float* __restrict__ bias,
                      const float* __restrict__ gamma,
                      const float* __restrict__ beta,
                      float* __restrict__ out) {
    const int row = row0 + blockIdx.x;
    const int tid = threadIdx.x;
    const int c4  = tid & 63;         // uint2 column (4 halves)
    const int par = tid >> 6;         // edge parity 0..3
    const uint2* f4 = reinterpret_cast<const uint2*>(feat);   // 64 per row

    __shared__ int2   s_meta[64];
    __shared__ float4 s_par[3][64];

    const int beg = g_off[row];
    const int end = g_off[row + 1];
    const float di = g_dinv[row];

    float4 a0 = make_float4(0.f,0.f,0.f,0.f), a1 = a0, a2 = a0, a3 = a0;
    if (par == 0) {   // self-loop
        fma4_h(a0, di * di, f4[(long)row * D_H4 + c4]);
    }

    for (int chunk = beg; chunk < end; chunk += 64) {
        int n = min(64, end - chunk);
        if (chunk != beg) __syncthreads();
        if (tid < n) s_meta[tid] = g_csr[chunk + tid];
        __syncthreads();
        int k = par;
        for (; k + 12 < n; k += 16) {
            int2 m0 = s_meta[k], m1 = s_meta[k + 4], m2 = s_meta[k + 8], m3 = s_meta[k + 12];
            uint2 v0 = f4[(long)m0.x * D_H4 + c4];
            uint2 v1 = f4[(long)m1.x * D_H4 + c4];
            uint2 v2 = f4[(long)m2.x * D_H4 + c4];
            uint2 v3 = f4[(long)m3.x * D_H4 + c4];
            fma4_h(a0, __int_as_float(m0.y), v0);
            fma4_h(a1, __int_as_float(m1.y), v1);
            fma4_h(a2, __int_as_float(m2.y), v2);
            fma4_h(a3, __int_as_float(m3.y), v3);
        }
        for (; k < n; k += 4) {
            int2 m = s_meta[k];
            fma4_h(a0, __int_as_float(m.y), f4[(long)m.x * D_H4 + c4]);
        }
    }

    float4 acc = make_float4((a0.x + a1.x) + (a2.x + a3.x),
                             (a0.y + a1.y) + (a2.y + a3.y),
                             (a0.z + a1.z) + (a2.z + a3.z),
                             (a0.w + a1.w) + (a2.w + a3.w));

    // combine the four parity groups
    __syncthreads();
    if (par != 0) s_par[par - 1][c4] = acc;
    __syncthreads();

    float4 t4 = make_float4(0.f, 0.f, 0.f, 0.f);
    if (par == 0) {
        float4 p1 = s_par[0][c4], p2 = s_par[1][c4], p3 = s_par[2][c4];
        acc.x += p1.x + p2.x + p3.x;
        acc.y += p1.y + p2.y + p3.y;
        acc.z += p1.z + p2.z + p3.z;
        acc.w += p1.w + p2.w + p3.w;
        int col = c4 * 4;
        float4 bb = *reinterpret_cast<const float4*>(bias + col);
        float4 r  = *reinterpret_cast<const float4*>(resid + (long)row * D_H + col);
        if (RELU) {
            t4.x = r.x + fmaxf(acc.x + bb.x, 0.0f);
            t4.y = r.y + fmaxf(acc.y + bb.y, 0.0f);
            t4.z = r.z + fmaxf(acc.z + bb.z, 0.0f);
            t4.w = r.w + fmaxf(acc.w + bb.w, 0.0f);
        } else {
            t4.x = r.x + acc.x + bb.x;
            t4.y = r.y + acc.y + bb.y;
            t4.z = r.z + acc.z + bb.z;
            t4.w = r.w + acc.w + bb.w;
        }
    }

    // LN stats over 256 values (non-par-0 threads contribute 0)
    float s  = (t4.x + t4.y) + (t4.z + t4.w);
    float sq = (t4.x * t4.x + t4.y * t4.y) + (t4.z * t4.z + t4.w * t4.w);
#pragma unroll
    for (int o = 16; o; o >>= 1) {
        s  += __shfl_xor_sync(0xFFFFFFFFu, s, o);
        sq += __shfl_xor_sync(0xFFFFFFFFu, sq, o);
    }
    __shared__ float ss[8], ssq[8];
    int wid = tid >> 5;
    if ((tid & 31) == 0) { ss[wid] = s; ssq[wid] = sq; }
    __syncthreads();
    float ts = 0.f, tq = 0.f;
#pragma unroll
    for (int i = 0; i < 8; i++) { ts += ss[i]; tq += ssq[i]; }
    float mu  = ts * (1.0f / D_H);
    float var = tq * (1.0f / D_H) - mu * mu;

    if (par == 0) {
        float rstd = rsqrtf(var + LN_EPS);
        int col = c4 * 4;
        float4 gm = *reinterpret_cast<const float4*>(gamma + col);
        float4 bt = *reinterpret_cast<const float4*>(beta + col);
        float4 o;
        o.x = (t4.x - mu) * rstd * gm.x + bt.x;
        o.y = (t4.y - mu) * rstd * gm.y + bt.y;
        o.z = (t4.z - mu) * rstd * gm.z + bt.z;
        o.w = (t4.w - mu) * rstd * gm.w + bt.w;
        *reinterpret_cast<float4*>(out + (long)row * D_H + col) = o;
    }
}

// ---------------- launch ----------------
extern "C" void kernel_launch(void* const* d_in, const int* in_sizes, int n_in,
                              void* d_out, int out_size) {
    const float* x      = (const float*)d_in[0];
    const int*   ei     = (const int*)d_in[1];     // [2,E] int32
    const float* ew     = (const float*)d_in[2];
    const float* W1     = (const float*)d_in[3];
    const float* b1     = (const float*)d_in[4];
    const float* W2     = (const float*)d_in[5];
    const float* b2     = (const float*)d_in[6];
    const float* Wres   = (const float*)d_in[7];
    const float* bres   = (const float*)d_in[8];
    const float* gamma1 = (const float*)d_in[9];
    const float* beta1  = (const float*)d_in[10];
    const float* gamma2 = (const float*)d_in[11];
    const float* beta2  = (const float*)d_in[12];
    float* out = (float*)d_out;

    const int E = in_sizes[2];
    const int* src = ei;
    const int* dst = ei + E;

    __half *p_h1h = nullptr, *p_h2h = nullptr;
    float *p_hres = nullptr, *p_h = nullptr;
    cudaGetSymbolAddress((void**)&p_h1h,  g_h1h);
    cudaGetSymbolAddress((void**)&p_h2h,  g_h2h);
    cudaGetSymbolAddress((void**)&p_hres, g_hres);
    cudaGetSymbolAddress((void**)&p_h,    g_h);

    // lazily-created side stream + events (host resources only)
    static cudaStream_t sideStream = nullptr;
    static cudaEvent_t  evFork = nullptr, evJoin = nullptr, evA = nullptr, evB = nullptr;
    if (!sideStream) {
        if (cudaStreamCreateWithFlags(&sideStream, cudaStreamNonBlocking) != cudaSuccess)
            sideStream = nullptr;
        if (sideStream) {
            cudaEventCreateWithFlags(&evFork, cudaEventDisableTiming);
            cudaEventCreateWithFlags(&evJoin, cudaEventDisableTiming);
            cudaEventCreateWithFlags(&evA,    cudaEventDisableTiming);
            cudaEventCreateWithFlags(&evB,    cudaEventDisableTiming);
        }
    }
    cudaStream_t cs = sideStream ? sideStream : (cudaStream_t)0;

    // fork: CSR build chain on side stream (4 kernels)
    if (sideStream) {
        cudaEventRecord(evFork, 0);
        cudaStreamWaitEvent(sideStream, evFork, 0);
    }
    degcnt_kernel<<<(E + 255) / 256, 256, 0, cs>>>(dst, ew, E);
    scan1_kernel<<<NB_SCAN, 256, 0, cs>>>();
    scan2_kernel<<<NB_SCAN, 256, 0, cs>>>(E);
    fill_kernel<<<(E + 255) / 256, 256, 0, cs>>>(src, dst, ew, E);
    if (sideStream) cudaEventRecord(evJoin, sideStream);

    const int nb = D_H / 128;                    // 2 col-blocks per matrix
    const int mblk_all = (N_NODES + 127) / 128;  // 157
    const int mblk_a   = H_SPLIT / 128;          // 79
    const int mblk_b   = (N_NODES - H_SPLIT + 127) / 128;  // 78

    // main stream (concurrent with CSR build):
    // h1(fp16) = x@W1 ; hres(fp32) = x@Wres + bres
    f16_gemm_kernel<D_IN><<<dim3(mblk_all, 2 * nb), 256>>>(
        x, 0, N_NODES, nb,
        W1, nullptr, p_h1h, nullptr,
        Wres, bres, nullptr, p_hres);

    // join: gather needs both CSR and GEMM results
    if (sideStream) cudaStreamWaitEvent((cudaStream_t)0, evJoin, 0);

    if (sideStream) {
        // pipelined middle: gather1_A -> {GEMM2_A || gather1_B} -> GEMM2_B
        gather_ln_kernel<true><<<H_SPLIT, 256>>>(
            0, p_h1h, p_hres, b1, gamma1, beta1, p_h);
        cudaEventRecord(evA, 0);
        cudaStreamWaitEvent(sideStream, evA, 0);
        gather_ln_kernel<true><<<N_NODES - H_SPLIT, 256, 0, sideStream>>>(
            H_SPLIT, p_h1h, p_hres, b1, gamma1, beta1, p_h);
        cudaEventRecord(evB, sideStream);

        f16_gemm_kernel<D_H><<<dim3(mblk_a, nb), 256>>>(
            p_h, 0, H_SPLIT, nb,
            W2, nullptr, p_h2h, nullptr,
            W2, nullptr, p_h2h, nullptr);
        cudaStreamWaitEvent((cudaStream_t)0, evB, 0);
        f16_gemm_kernel<D_H><<<dim3(mblk_b, nb), 256>>>(
            p_h, H_SPLIT, N_NODES, nb,
            W2, nullptr, p_h2h, nullptr,
            W2, nullptr, p_h2h, nullptr);
    } else {
        // serial fallback
        gather_ln_kernel<true><<<N_NODES, 256>>>(
            0, p_h1h, p_hres, b1, gamma1, beta1, p_h);
        f16_gemm_kernel<D_H><<<dim3(mblk_all, nb), 256>>>(
            p_h, 0, N_NODES, nb,
            W2, nullptr, p_h2h, nullptr,
            W2, nullptr, p_h2h, nullptr);
    }

    // hop 1: gather(h2) + b2 + h residual + LN -> out (fp32)
    gather_ln_kernel<false><<<N_NODES, 256>>>(
        0, p_h2h, p_h, b2, gamma2, beta2, out);
}